// round 4
// baseline (speedup 1.0000x reference)
#include <cuda_runtime.h>
#include <cstddef>

// CTC loss forward (log-semiring alpha recursion), k2-style tot_scores.
// B=32, T=800, C=5000, L=100, S=2L+1=201.
//
// Pipeline (3 kernels, graph-capturable, no allocations):
//  1) gather_kernel : emit[b][t][j] = log_probs[b,t, j==0 ? 0 : targets[b,j-1]]
//     (full-chip parallel; converts the huge random gather into a small dense
//      scratch that fits in L2)
//  2) ctc_alpha_kernel : one block per utterance, 201 states across threads,
//     double-buffered smem alpha, one barrier per time step, depth-2 register
//     prefetch of emissions (L2 hits).
//  3) reduce_kernel : deterministic serial reduction over 32 utterances.

#define Bb 32
#define Tt 800
#define Cc 5000
#define Ll 100
#define Ss 201          // 2L+1
#define EP 104          // padded emit row stride (floats)
#define NEGV (-1e30f)

__device__ float g_emit[(size_t)Bb * Tt * EP];
__device__ float g_tot[Bb];

// ---------------------------------------------------------------------------
// Kernel 1: gather emissions. One thread per (b, t, j), j in [0, L].
// ---------------------------------------------------------------------------
__global__ void gather_kernel(const float* __restrict__ lp,
                              const int* __restrict__ targets) {
    int i = blockIdx.x * blockDim.x + threadIdx.x;
    const int total = Bb * Tt * (Ll + 1);
    if (i >= total) return;
    int j  = i % (Ll + 1);
    int bt = i / (Ll + 1);
    int b  = bt / Tt;
    int c  = (j == 0) ? 0 : targets[b * Ll + (j - 1)];
    g_emit[(size_t)bt * EP + j] = lp[(size_t)bt * Cc + c];
}

// ---------------------------------------------------------------------------
// Kernel 2: alpha recursion. grid = B blocks, 256 threads (state s = tid).
// ---------------------------------------------------------------------------
__global__ __launch_bounds__(256, 1)
void ctc_alpha_kernel(const int* __restrict__ targets,
                      const int* __restrict__ ilen,
                      const int* __restrict__ tlen) {
    // sh[buf][0..1] are permanent NEG padding; state s lives at index 2+s.
    __shared__ float sh[2][Ss + 2];

    const int b = blockIdx.x;
    const int s = threadIdx.x;
    const int il = ilen[b];
    const int last = il - 1;          // il >= 601 for this problem

    if (s < 2) { sh[0][s] = NEGV; sh[1][s] = NEGV; }

    // Per-thread static params: emission column + CTC skip-transition mask.
    int  eidx = 0;
    bool skip = false;
    if (s < Ss && (s & 1)) {
        int j = s >> 1;               // (s-1)/2 for odd s
        eidx = 1 + j;
        int tg  = targets[b * Ll + j];
        int tgp = (j > 0) ? targets[b * Ll + j - 1] : -1;
        skip = (tg != tgp);           // blank (even s) never skips
    }
    const float* __restrict__ pe = g_emit + (size_t)b * Tt * EP + eidx;

    // alpha0: only states 0 and 1 are live, with emissions at t=0.
    if (s < Ss) {
        float v = NEGV;
        if (s == 0) v = g_emit[(size_t)b * Tt * EP + 0];
        if (s == 1) v = g_emit[(size_t)b * Tt * EP + 1];
        sh[0][2 + s] = v;
    }

    // Depth-2 emission prefetch ring (reads are L2 hits into g_emit).
    int t1 = (1 <= last) ? 1 : last;
    int t2 = (2 <= last) ? 2 : last;
    float e1 = pe[(size_t)EP * t1];
    float e2 = pe[(size_t)EP * t2];

    float a1 = (s < Ss) ? sh[0][2 + s] : NEGV;   // own previous alpha in reg
    __syncthreads();

    int cur = 0;
    for (int t = 1; t <= last; ++t) {
        float ec = e1; e1 = e2;
        int tp = t + 2; if (tp > last) tp = last;
        e2 = pe[(size_t)EP * tp];                // issue load 2 steps ahead

        if (s < Ss) {
            float a2 = sh[cur][1 + s];           // state s-1 (pad covers s=0)
            float a3 = skip ? sh[cur][s] : NEGV; // state s-2 (pad covers s<2)
            float m  = fmaxf(a1, fmaxf(a2, a3));
            float sum = __expf(a1 - m) + __expf(a2 - m) + __expf(a3 - m);
            float na  = m + __logf(sum) + ec;
            sh[cur ^ 1][2 + s] = na;
            a1 = na;
        }
        __syncthreads();
        cur ^= 1;
    }

    if (s == 0) {
        int Lb = tlen[b];
        float x = sh[cur][2 + 2 * Lb];
        float y = sh[cur][2 + 2 * Lb - 1];
        float m = fmaxf(x, y);
        g_tot[b] = m + __logf(__expf(x - m) + __expf(y - m));
    }
}

// ---------------------------------------------------------------------------
// Kernel 3: deterministic serial reduction.
// ---------------------------------------------------------------------------
__global__ void reduce_kernel(const int* __restrict__ ilen,
                              float* __restrict__ out) {
    if (blockIdx.x == 0 && threadIdx.x == 0) {
        float ts = 0.0f;
        long long tf = 0, af = 0;
        for (int b = 0; b < Bb; ++b) {
            float tot = g_tot[b];
            int il = ilen[b];
            af += il;
            if (tot > NEGV * 0.5f) { ts += tot; tf += il; }
        }
        out[0] = ts;
        out[1] = (float)tf;
        out[2] = (float)af;
    }
}

// ---------------------------------------------------------------------------
extern "C" void kernel_launch(void* const* d_in, const int* in_sizes, int n_in,
                              void* d_out, int out_size) {
    const float* lp      = (const float*)d_in[0];  // nnet_output [B,T,C] f32
    const int*   targets = (const int*)  d_in[1];  // [B,L] i32
    const int*   ilen    = (const int*)  d_in[2];  // [B] i32
    const int*   tlen    = (const int*)  d_in[3];  // [B] i32

    const int total = Bb * Tt * (Ll + 1);
    gather_kernel<<<(total + 255) / 256, 256>>>(lp, targets);
    ctc_alpha_kernel<<<Bb, 256>>>(targets, ilen, tlen);
    reduce_kernel<<<1, 32>>>(ilen, (float*)d_out);
}

// round 5
// speedup vs baseline: 1.4985x; 1.4985x over previous
#include <cuda_runtime.h>
#include <cstddef>

// CTC loss forward (log-semiring alpha recursion), k2-style tot_scores.
// B=32, T=800, C=5000, L=100, S=2L+1=201.
//
// R5 changes vs R4 (which ran 280us: gather 43us, alpha ~230us):
//  * alpha: TRUE depth-4 register prefetch ring for emissions (unroll-4 so
//    ptxas renames the ring slots; R4's ring collapsed to depth-1 and put a
//    234-262cyc L2 hit on the per-step critical chain -> ~500 cyc/step).
//  * alpha: log2-domain recursion (emissions pre-scaled by log2(e) in the
//    gather; raw ex2/lg2 on the chain; single *ln2 at the end).
//  * alpha: 224 threads (7 warps) exactly covering S=201.

#define Bb 32
#define Tt 800
#define Cc 5000
#define Ll 100
#define Ss 201          // 2L+1
#define EP 104          // padded emit row stride (floats)
#define NEGV (-1e30f)
#define LOG2E 1.4426950408889634f
#define LN2   0.6931471805599453f

__device__ float g_emit[(size_t)Bb * Tt * EP];
__device__ float g_tot[Bb];

__device__ __forceinline__ float ex2f(float x) {
    float y; asm("ex2.approx.ftz.f32 %0, %1;" : "=f"(y) : "f"(x)); return y;
}
__device__ __forceinline__ float lg2f(float x) {
    float y; asm("lg2.approx.ftz.f32 %0, %1;" : "=f"(y) : "f"(x)); return y;
}

// ---------------------------------------------------------------------------
// Kernel 1: gather emissions, pre-scaled into log2 domain.
// emit[b][t][j] = log2e * lp[b, t, j==0 ? 0 : targets[b,j-1]]
// ---------------------------------------------------------------------------
__global__ void gather_kernel(const float* __restrict__ lp,
                              const int* __restrict__ targets) {
    int i = blockIdx.x * blockDim.x + threadIdx.x;
    const int total = Bb * Tt * (Ll + 1);
    if (i >= total) return;
    int j  = i % (Ll + 1);
    int bt = i / (Ll + 1);
    int b  = bt / Tt;
    int c  = (j == 0) ? 0 : targets[b * Ll + (j - 1)];
    g_emit[(size_t)bt * EP + j] = LOG2E * lp[(size_t)bt * Cc + c];
}

// ---------------------------------------------------------------------------
// Kernel 2: alpha recursion in log2 domain. grid = B blocks, 224 threads.
// ---------------------------------------------------------------------------
__global__ __launch_bounds__(224, 1)
void ctc_alpha_kernel(const int* __restrict__ targets,
                      const int* __restrict__ ilen,
                      const int* __restrict__ tlen) {
    // sh[buf][0..1] are permanent NEG padding; state s lives at index 2+s.
    __shared__ float sh[2][Ss + 2];

    const int b = blockIdx.x;
    const int s = threadIdx.x;
    const int last = ilen[b] - 1;     // >= 600 for this problem

    if (s < 2) { sh[0][s] = NEGV; sh[1][s] = NEGV; }

    // Per-thread static params: emission column + CTC skip-transition mask.
    int  eidx = 0;
    bool skip = false;
    if (s < Ss && (s & 1)) {
        int j = s >> 1;
        eidx = 1 + j;
        int tg  = targets[b * Ll + j];
        int tgp = (j > 0) ? targets[b * Ll + j - 1] : -1;
        skip = (tg != tgp);           // blank (even s) never skips
    }
    const float* __restrict__ pe = g_emit + (size_t)b * Tt * EP + eidx;

    // alpha0 (log2 domain): only states 0 and 1 are live.
    float a1 = NEGV;                  // own previous alpha, kept in a register
    if (s < Ss) {
        if (s == 0) a1 = g_emit[(size_t)b * Tt * EP + 0];
        if (s == 1) a1 = g_emit[(size_t)b * Tt * EP + 1];
        sh[0][2 + s] = a1;
    }

    // Depth-4 emission prefetch ring. unroll-4 below makes each slot a
    // distinct renamed register, so a load issued at step t is consumed at
    // step t+4 (~4 steps of slack >> L2 hit latency).
    float er[4];
#pragma unroll
    for (int k = 0; k < 4; ++k) {
        int tt = 1 + k; if (tt > last) tt = last;
        er[k] = pe[(size_t)EP * tt];
    }

    __syncthreads();

    int cur = 0;
#pragma unroll 4
    for (int t = 1; t <= last; ++t) {
        const int k = (t - 1) & 3;
        float ec = er[k];                       // copy out, then refill slot
        int tp = t + 4; if (tp > last) tp = last;
        er[k] = pe[(size_t)EP * tp];

        if (s < Ss) {
            float a2 = sh[cur][1 + s];          // state s-1 (pad covers s=0)
            float a3 = skip ? sh[cur][s] : NEGV;// state s-2 (pad covers s<2)
            float m  = fmaxf(a1, fmaxf(a2, a3));
            float sum = ex2f(a1 - m) + ex2f(a2 - m) + ex2f(a3 - m);
            float na  = m + lg2f(sum) + ec;
            sh[cur ^ 1][2 + s] = na;
            a1 = na;
        }
        __syncthreads();
        cur ^= 1;
    }

    if (s == 0) {
        int Lb = tlen[b];
        float x = sh[cur][2 + 2 * Lb];
        float y = sh[cur][2 + 2 * Lb - 1];
        float m = fmaxf(x, y);
        g_tot[b] = LN2 * (m + lg2f(ex2f(x - m) + ex2f(y - m)));
    }
}

// ---------------------------------------------------------------------------
// Kernel 3: deterministic serial reduction.
// ---------------------------------------------------------------------------
__global__ void reduce_kernel(const int* __restrict__ ilen,
                              float* __restrict__ out) {
    if (blockIdx.x == 0 && threadIdx.x == 0) {
        float ts = 0.0f;
        long long tf = 0, af = 0;
        for (int b = 0; b < Bb; ++b) {
            float tot = g_tot[b];
            int il = ilen[b];
            af += il;
            if (tot > NEGV * 0.5f) { ts += tot; tf += il; }
        }
        out[0] = ts;
        out[1] = (float)tf;
        out[2] = (float)af;
    }
}

// ---------------------------------------------------------------------------
extern "C" void kernel_launch(void* const* d_in, const int* in_sizes, int n_in,
                              void* d_out, int out_size) {
    const float* lp      = (const float*)d_in[0];  // nnet_output [B,T,C] f32
    const int*   targets = (const int*)  d_in[1];  // [B,L] i32
    const int*   ilen    = (const int*)  d_in[2];  // [B] i32
    const int*   tlen    = (const int*)  d_in[3];  // [B] i32

    const int total = Bb * Tt * (Ll + 1);
    gather_kernel<<<(total + 255) / 256, 256>>>(lp, targets);
    ctc_alpha_kernel<<<Bb, 224>>>(targets, ilen, tlen);
    reduce_kernel<<<1, 32>>>(ilen, (float*)d_out);
}

// round 6
// speedup vs baseline: 2.1316x; 1.4225x over previous
#include <cuda_runtime.h>
#include <cstddef>

// CTC loss forward, fused single-kernel version.
// B=32, T=800, C=5000, L=100, S=2L+1=201.
//
// R6 vs R5 (187us = gather 42 + alpha 142 + reduce 3):
//  * gather kernel ELIMINATED: emissions are per-thread strided LDGs straight
//    from nnet_output, hidden behind a depth-8 register ring (8 steps of slack
//    ~1100cyc >> 577cyc DRAM latency) -> the 250MB gather overlaps the alpha
//    recursion for free.
//  * alpha carried as (base, sum) pairs (alpha = base + log2(sum)): the per-
//    step lg2 disappears from the serial chain (folded once per 32 steps;
//    3^32 < f32 max). Only 2-3 ex2 per state per step.
//  * 2 states per thread (128 threads, 4 warps): odd state's s-1 predecessor
//    is the thread's own even state (registers); cross-thread exchange is a
//    single float4 STS.128/LDS.128 per step. Blank (even) states have no skip
//    arc -> 2-term update.

#define Bb 32
#define Tt 800
#define Cc 5000
#define Ll 100
#define NT 101            // thread i owns states 2i, 2i+1
#define NEGV (-1e30f)
#define LOG2E 1.4426950408889634f
#define LN2   0.6931471805599453f
#define DPF 8             // emission prefetch depth
#define RENORM 32

__device__ float g_tot[Bb];

__device__ __forceinline__ float ex2f(float x) {
    float y; asm("ex2.approx.ftz.f32 %0, %1;" : "=f"(y) : "f"(x)); return y;
}
__device__ __forceinline__ float lg2f(float x) {
    float y; asm("lg2.approx.ftz.f32 %0, %1;" : "=f"(y) : "f"(x)); return y;
}

// ---------------------------------------------------------------------------
// Fused gather + alpha recursion. grid = B blocks, 128 threads.
// ---------------------------------------------------------------------------
__global__ __launch_bounds__(128, 1)
void ctc_alpha_fused(const float* __restrict__ lp,
                     const int* __restrict__ targets,
                     const int* __restrict__ ilen,
                     const int* __restrict__ tlen)
{
    // sh[buf][0] is a permanent dead pad (base=NEG, sum=0 -> contributes 0).
    // Thread i stores its (be,se,bo,so) at slot i+1; reads neighbor at slot i.
    __shared__ float4 sh[2][NT + 1];

    const int b = blockIdx.x;
    const int i = threadIdx.x;
    const int last = ilen[b] - 1;        // >= 600 for this problem

    // Per-thread static params. tg = class of odd state 2i+1.
    const int  tg   = (i < Ll) ? targets[b * Ll + i] : 0;
    const int  tgp  = (i >= 1 && i <= Ll) ? targets[b * Ll + i - 1] : -1;
    const bool skip = (tg != tgp);       // skip arc for odd state 2i+1

    const float* __restrict__ rowb = lp + (size_t)b * Tt * Cc;

    if (i == 0) {
        sh[0][0] = make_float4(NEGV, 0.f, NEGV, 0.f);
        sh[1][0] = make_float4(NEGV, 0.f, NEGV, 0.f);
    }

    // t=0 init (log2 domain): only states 0 and 1 live. alpha = base + lg2(sum).
    float se = 1.f, so = 1.f;
    float be = (i == 0) ? LOG2E * rowb[0]  : NEGV;
    float bo = (i == 0) ? LOG2E * rowb[tg] : NEGV;
    if (i < NT) sh[0][i + 1] = make_float4(be, se, bo, so);

    // Depth-8 emission prefetch rings: blank (col 0, broadcast) + own target col.
    float eb[DPF], eo[DPF];
#pragma unroll
    for (int k = 0; k < DPF; ++k) {
        int tt = 1 + k; if (tt > last) tt = last;
        eb[k] = rowb[(size_t)tt * Cc];
        eo[k] = rowb[(size_t)tt * Cc + tg];
    }
    __syncthreads();

    int cur = 0;
#pragma unroll 8
    for (int t = 1; t <= last; ++t) {
        const int k = (t - 1) & (DPF - 1);
        float ecb = LOG2E * eb[k];
        float eco = LOG2E * eo[k];
        int tp = t + DPF; if (tp > last) tp = last;
        eb[k] = rowb[(size_t)tp * Cc];
        eo[k] = rowb[(size_t)tp * Cc + tg];

        float4 nb = sh[cur][i];          // thread i-1's states (2i-2, 2i-1)
        if (i < NT) {
            // even state 2i (blank): preds = self, state 2i-1 (nb odd).
            float me = fmaxf(be, nb.z);
            float te = se * ex2f(be - me) + nb.w * ex2f(nb.z - me);
            // odd state 2i+1: preds = self, own even (regs), nb odd if skip.
            float b3 = skip ? nb.z : NEGV;
            float s3 = skip ? nb.w : 0.f;
            float mo = fmaxf(fmaxf(bo, be), b3);
            float to = so * ex2f(bo - mo) + se * ex2f(be - mo)
                     + s3 * ex2f(b3 - mo);
            be = me + ecb; se = te;
            bo = mo + eco; so = to;
            if ((t & (RENORM - 1)) == 0) {   // periodic fold, off 31/32 steps
                be = fmaxf(be + lg2f(se), NEGV); se = 1.f;
                bo = fmaxf(bo + lg2f(so), NEGV); so = 1.f;
            }
            sh[cur ^ 1][i + 1] = make_float4(be, se, bo, so);
        }
        __syncthreads();
        cur ^= 1;
    }

    if (i == 0) {
        int Lb = tlen[b];
        float4 ve = sh[cur][Lb + 1];     // even of thread Lb   -> state 2Lb
        float4 vo = sh[cur][Lb];         // odd  of thread Lb-1 -> state 2Lb-1
        float x = ve.x + lg2f(ve.y);
        float y = vo.z + lg2f(vo.w);
        float m = fmaxf(x, y);
        g_tot[b] = LN2 * (m + lg2f(ex2f(x - m) + ex2f(y - m)));
    }
}

// ---------------------------------------------------------------------------
// Deterministic serial reduction.
// ---------------------------------------------------------------------------
__global__ void reduce_kernel(const int* __restrict__ ilen,
                              float* __restrict__ out) {
    if (blockIdx.x == 0 && threadIdx.x == 0) {
        float ts = 0.0f;
        long long tf = 0, af = 0;
        for (int b = 0; b < Bb; ++b) {
            float tot = g_tot[b];
            int il = ilen[b];
            af += il;
            if (tot > NEGV * 0.5f) { ts += tot; tf += il; }
        }
        out[0] = ts;
        out[1] = (float)tf;
        out[2] = (float)af;
    }
}

// ---------------------------------------------------------------------------
extern "C" void kernel_launch(void* const* d_in, const int* in_sizes, int n_in,
                              void* d_out, int out_size) {
    const float* lp      = (const float*)d_in[0];  // nnet_output [B,T,C] f32
    const int*   targets = (const int*)  d_in[1];  // [B,L] i32
    const int*   ilen    = (const int*)  d_in[2];  // [B] i32
    const int*   tlen    = (const int*)  d_in[3];  // [B] i32

    ctc_alpha_fused<<<Bb, 128>>>(lp, targets, ilen, tlen);
    reduce_kernel<<<1, 32>>>(ilen, (float*)d_out);
}

// round 7
// speedup vs baseline: 2.1957x; 1.0301x over previous
#include <cuda_runtime.h>
#include <cstddef>

// CTC loss forward, fused single-kernel version.
// B=32, T=800, C=5000, L=100, S=2L+1=201.
//
// R6 vs R5 (187us = gather 42 + alpha 142 + reduce 3):
//  * gather kernel ELIMINATED: emissions are per-thread strided LDGs straight
//    from nnet_output, hidden behind a depth-8 register ring (8 steps of slack
//    ~1100cyc >> 577cyc DRAM latency) -> the 250MB gather overlaps the alpha
//    recursion for free.
//  * alpha carried as (base, sum) pairs (alpha = base + log2(sum)): the per-
//    step lg2 disappears from the serial chain (folded once per 32 steps;
//    3^32 < f32 max). Only 2-3 ex2 per state per step.
//  * 2 states per thread (128 threads, 4 warps): odd state's s-1 predecessor
//    is the thread's own even state (registers); cross-thread exchange is a
//    single float4 STS.128/LDS.128 per step. Blank (even) states have no skip
//    arc -> 2-term update.

#define Bb 32
#define Tt 800
#define Cc 5000
#define Ll 100
#define NT 101            // thread i owns states 2i, 2i+1
#define NEGV (-1e30f)
#define LOG2E 1.4426950408889634f
#define LN2   0.6931471805599453f
#define DPF 8             // emission prefetch depth
#define RENORM 32

__device__ float g_tot[Bb];

__device__ __forceinline__ float ex2f(float x) {
    float y; asm("ex2.approx.ftz.f32 %0, %1;" : "=f"(y) : "f"(x)); return y;
}
__device__ __forceinline__ float lg2f(float x) {
    float y; asm("lg2.approx.ftz.f32 %0, %1;" : "=f"(y) : "f"(x)); return y;
}

// ---------------------------------------------------------------------------
// Fused gather + alpha recursion. grid = B blocks, 128 threads.
// ---------------------------------------------------------------------------
__global__ __launch_bounds__(128, 1)
void ctc_alpha_fused(const float* __restrict__ lp,
                     const int* __restrict__ targets,
                     const int* __restrict__ ilen,
                     const int* __restrict__ tlen)
{
    // sh[buf][0] is a permanent dead pad (base=NEG, sum=0 -> contributes 0).
    // Thread i stores its (be,se,bo,so) at slot i+1; reads neighbor at slot i.
    __shared__ float4 sh[2][NT + 1];

    const int b = blockIdx.x;
    const int i = threadIdx.x;
    const int last = ilen[b] - 1;        // >= 600 for this problem

    // Per-thread static params. tg = class of odd state 2i+1.
    const int  tg   = (i < Ll) ? targets[b * Ll + i] : 0;
    const int  tgp  = (i >= 1 && i <= Ll) ? targets[b * Ll + i - 1] : -1;
    const bool skip = (tg != tgp);       // skip arc for odd state 2i+1

    const float* __restrict__ rowb = lp + (size_t)b * Tt * Cc;

    if (i == 0) {
        sh[0][0] = make_float4(NEGV, 0.f, NEGV, 0.f);
        sh[1][0] = make_float4(NEGV, 0.f, NEGV, 0.f);
    }

    // t=0 init (log2 domain): only states 0 and 1 live. alpha = base + lg2(sum).
    float se = 1.f, so = 1.f;
    float be = (i == 0) ? LOG2E * rowb[0]  : NEGV;
    float bo = (i == 0) ? LOG2E * rowb[tg] : NEGV;
    if (i < NT) sh[0][i + 1] = make_float4(be, se, bo, so);

    // Depth-8 emission prefetch rings: blank (col 0, broadcast) + own target col.
    float eb[DPF], eo[DPF];
#pragma unroll
    for (int k = 0; k < DPF; ++k) {
        int tt = 1 + k; if (tt > last) tt = last;
        eb[k] = rowb[(size_t)tt * Cc];
        eo[k] = rowb[(size_t)tt * Cc + tg];
    }
    __syncthreads();

    int cur = 0;
#pragma unroll 8
    for (int t = 1; t <= last; ++t) {
        const int k = (t - 1) & (DPF - 1);
        float ecb = LOG2E * eb[k];
        float eco = LOG2E * eo[k];
        int tp = t + DPF; if (tp > last) tp = last;
        eb[k] = rowb[(size_t)tp * Cc];
        eo[k] = rowb[(size_t)tp * Cc + tg];

        float4 nb = sh[cur][i];          // thread i-1's states (2i-2, 2i-1)
        if (i < NT) {
            // even state 2i (blank): preds = self, state 2i-1 (nb odd).
            float me = fmaxf(be, nb.z);
            float te = se * ex2f(be - me) + nb.w * ex2f(nb.z - me);
            // odd state 2i+1: preds = self, own even (regs), nb odd if skip.
            float b3 = skip ? nb.z : NEGV;
            float s3 = skip ? nb.w : 0.f;
            float mo = fmaxf(fmaxf(bo, be), b3);
            float to = so * ex2f(bo - mo) + se * ex2f(be - mo)
                     + s3 * ex2f(b3 - mo);
            be = me + ecb; se = te;
            bo = mo + eco; so = to;
            if ((t & (RENORM - 1)) == 0) {   // periodic fold, off 31/32 steps
                be = fmaxf(be + lg2f(se), NEGV); se = 1.f;
                bo = fmaxf(bo + lg2f(so), NEGV); so = 1.f;
            }
            sh[cur ^ 1][i + 1] = make_float4(be, se, bo, so);
        }
        __syncthreads();
        cur ^= 1;
    }

    if (i == 0) {
        int Lb = tlen[b];
        float4 ve = sh[cur][Lb + 1];     // even of thread Lb   -> state 2Lb
        float4 vo = sh[cur][Lb];         // odd  of thread Lb-1 -> state 2Lb-1
        float x = ve.x + lg2f(ve.y);
        float y = vo.z + lg2f(vo.w);
        float m = fmaxf(x, y);
        g_tot[b] = LN2 * (m + lg2f(ex2f(x - m) + ex2f(y - m)));
    }
}

// ---------------------------------------------------------------------------
// Deterministic serial reduction.
// ---------------------------------------------------------------------------
__global__ void reduce_kernel(const int* __restrict__ ilen,
                              float* __restrict__ out) {
    if (blockIdx.x == 0 && threadIdx.x == 0) {
        float ts = 0.0f;
        long long tf = 0, af = 0;
        for (int b = 0; b < Bb; ++b) {
            float tot = g_tot[b];
            int il = ilen[b];
            af += il;
            if (tot > NEGV * 0.5f) { ts += tot; tf += il; }
        }
        out[0] = ts;
        out[1] = (float)tf;
        out[2] = (float)af;
    }
}

// ---------------------------------------------------------------------------
extern "C" void kernel_launch(void* const* d_in, const int* in_sizes, int n_in,
                              void* d_out, int out_size) {
    const float* lp      = (const float*)d_in[0];  // nnet_output [B,T,C] f32
    const int*   targets = (const int*)  d_in[1];  // [B,L] i32
    const int*   ilen    = (const int*)  d_in[2];  // [B] i32
    const int*   tlen    = (const int*)  d_in[3];  // [B] i32

    ctc_alpha_fused<<<Bb, 128>>>(lp, targets, ilen, tlen);
    reduce_kernel<<<1, 32>>>(ilen, (float*)d_out);
}